// round 5
// baseline (speedup 1.0000x reference)
#include <cuda_runtime.h>
#include <math.h>

#define BLOCK   256
#define KNN     16
#define HID     64
#define NPTS    65536
#define NBATCH  4

// Scratch: per-batch xyz in AoS float4 (w unused). 4 * 65536 * 16B = 4 MB.
__device__ float4 g_xyz4[NBATCH * NPTS];

// ---------------- Kernel 1: transpose pos [B,3,N] -> float4 [B,N] ----------------
// Each thread handles 4 consecutive points: 3 float4 reads, 4 float4 writes.
__global__ __launch_bounds__(256) void transpose_pos_kernel(
    const float* __restrict__ pos, int N)
{
    const int q  = blockIdx.x * 256 + threadIdx.x;    // quad index, 0 .. B*N/4-1
    const int i  = q * 4;
    const int bb = i >> 16;                           // N = 65536
    const int n  = i & (NPTS - 1);
    const float* px = pos + (size_t)bb * 3 * N;

    const float4 vx = *reinterpret_cast<const float4*>(px + n);
    const float4 vy = *reinterpret_cast<const float4*>(px + N + n);
    const float4 vz = *reinterpret_cast<const float4*>(px + 2 * N + n);

    float4* o = g_xyz4 + i;
    o[0] = make_float4(vx.x, vy.x, vz.x, 0.0f);
    o[1] = make_float4(vx.y, vy.y, vz.y, 0.0f);
    o[2] = make_float4(vx.z, vy.z, vz.z, 0.0f);
    o[3] = make_float4(vx.w, vy.w, vz.w, 0.0f);
}

// ---------------- Kernel 2: features + matvec, warp-autonomous ----------------
// __launch_bounds__(256, 5): cap regs ~51 -> 40 warps/SM (occ ~62%).
__global__ __launch_bounds__(BLOCK, 5) void point_embed_kernel(
    const int*   __restrict__ idx,        // [B,N,K] int32
    const float* __restrict__ dist,       // [B,N,K]
    const float* __restrict__ W,          // [10,64]
    const float* __restrict__ bias,       // [64]
    float* __restrict__ out,              // [B,N,64]
    int N)
{
    // Per-warp private tile: no block-wide barrier anywhere.
    __shared__ float feat_s[BLOCK / 32][10][32];

    const int t = threadIdx.x;
    const int w = t >> 5;
    const int l = t & 31;

    const long long base_pt = (long long)blockIdx.x * BLOCK;   // block inside one batch
    const int bb = (int)(base_pt / N);
    const int n  = (int)(base_pt % N) + t;

    const float4* xb = g_xyz4 + (size_t)bb * N;

    const float4 s = __ldg(xb + n);                 // self point, one 16B load

    const int*   ip = idx  + ((size_t)bb * N + n) * KNN;
    const float* dp = dist + ((size_t)bb * N + n) * KNN;

    float mx = -INFINITY, my = -INFINITY, mz = -INFINITY;   // max neighbor
    float nx =  INFINITY, ny =  INFINITY, nz =  INFINITY;   // min neighbor
    float md = -INFINITY;                                    // max dist

    #pragma unroll
    for (int k = 0; k < KNN; k += 4) {
        int4 jj = *reinterpret_cast<const int4*>(ip + k);    // 16B aligned
        const float4 a = __ldg(xb + jj.x);   // one line per neighbor
        const float4 b = __ldg(xb + jj.y);
        const float4 c = __ldg(xb + jj.z);
        const float4 d = __ldg(xb + jj.w);
        mx = fmaxf(fmaxf(fmaxf(mx, a.x), fmaxf(b.x, c.x)), d.x);
        my = fmaxf(fmaxf(fmaxf(my, a.y), fmaxf(b.y, c.y)), d.y);
        mz = fmaxf(fmaxf(fmaxf(mz, a.z), fmaxf(b.z, c.z)), d.z);
        nx = fminf(fminf(fminf(nx, a.x), fminf(b.x, c.x)), d.x);
        ny = fminf(fminf(fminf(ny, a.y), fminf(b.y, c.y)), d.y);
        nz = fminf(fminf(fminf(nz, a.z), fminf(b.z, c.z)), d.z);
    }

    #pragma unroll
    for (int k = 0; k < KNN; k += 4) {
        float4 d4 = *reinterpret_cast<const float4*>(dp + k);
        md = fmaxf(md, fmaxf(fmaxf(d4.x, d4.y), fmaxf(d4.z, d4.w)));
    }

    feat_s[w][0][l] = s.x;
    feat_s[w][1][l] = s.y;
    feat_s[w][2][l] = s.z;
    feat_s[w][3][l] = mx;
    feat_s[w][4][l] = my;
    feat_s[w][5][l] = mz;
    feat_s[w][6][l] = s.x - nx;   // max(ext - nbr) = ext - min(nbr)
    feat_s[w][7][l] = s.y - ny;
    feat_s[w][8][l] = s.z - nz;
    feat_s[w][9][l] = md;

    __syncwarp();

    // Phase 2 (per-warp): lane l owns channels {2l, 2l+1}; loop 32 points.
    const float2* W2 = reinterpret_cast<const float2*>(W);     // [10][32] float2
    float2 wc[10];
    #pragma unroll
    for (int c = 0; c < 10; c++) wc[c] = __ldg(W2 + c * 32 + l);
    const float2 bv = __ldg(reinterpret_cast<const float2*>(bias) + l);

    float2* ob = reinterpret_cast<float2*>(out + (base_pt + (long long)w * 32) * HID);

    #pragma unroll 8
    for (int p = 0; p < 32; p++) {
        float2 acc = bv;
        #pragma unroll
        for (int c = 0; c < 10; c++) {
            const float f = feat_s[w][c][p];      // warp broadcast, conflict-free
            acc.x = fmaf(f, wc[c].x, acc.x);
            acc.y = fmaf(f, wc[c].y, acc.y);
        }
        acc.x = fmaxf(acc.x, 0.0f);
        acc.y = fmaxf(acc.y, 0.0f);
        ob[p * 32 + l] = acc;                      // warp writes 256B contiguous
    }
}

extern "C" void kernel_launch(void* const* d_in, const int* in_sizes, int n_in,
                              void* d_out, int out_size) {
    const float* pos  = (const float*)d_in[0];   // [B,3,N] f32
    const int*   idx  = (const int*)d_in[1];     // [B,N,K] i32
    const float* dist = (const float*)d_in[2];   // [B,N,K] f32
    const float* W    = (const float*)d_in[3];   // [10,64] f32
    const float* bias = (const float*)d_in[4];   // [64]    f32
    float*       out  = (float*)d_out;           // [B,N,64] f32

    const int N  = NPTS;
    const long long BN = (long long)out_size / HID;   // B*N total points

    transpose_pos_kernel<<<(int)(BN / 1024), 256>>>(pos, N);
    point_embed_kernel<<<(int)(BN / BLOCK), BLOCK>>>(idx, dist, W, bias, out, N);
}

// round 6
// speedup vs baseline: 1.2883x; 1.2883x over previous
#include <cuda_runtime.h>
#include <math.h>

#define BLOCK   256
#define PTS_PER_BLOCK 512
#define KNN     16
#define HID     64
#define NPTS    65536
#define NBATCH  4

// Scratch: per-batch xyz in AoS float4 (w unused). 4 * 65536 * 16B = 4 MB.
__device__ float4 g_xyz4[NBATCH * NPTS];

// ---------------- Kernel 1: transpose pos [B,3,N] -> float4 [B,N] ----------------
__global__ __launch_bounds__(256) void transpose_pos_kernel(
    const float* __restrict__ pos, int N)
{
    const int q  = blockIdx.x * 256 + threadIdx.x;    // quad index
    const int i  = q * 4;
    const int bb = i >> 16;                           // N = 65536
    const int n  = i & (NPTS - 1);
    const float* px = pos + (size_t)bb * 3 * N;

    const float4 vx = *reinterpret_cast<const float4*>(px + n);
    const float4 vy = *reinterpret_cast<const float4*>(px + N + n);
    const float4 vz = *reinterpret_cast<const float4*>(px + 2 * N + n);

    float4* o = g_xyz4 + i;
    o[0] = make_float4(vx.x, vy.x, vz.x, 0.0f);
    o[1] = make_float4(vx.y, vy.y, vz.y, 0.0f);
    o[2] = make_float4(vx.z, vy.z, vz.z, 0.0f);
    o[3] = make_float4(vx.w, vy.w, vz.w, 0.0f);
}

// ---------------- Kernel 2: 2 points/thread, warp-autonomous ----------------
__global__ __launch_bounds__(BLOCK) void point_embed_kernel(
    const int*   __restrict__ idx,        // [B,N,K] int32
    const float* __restrict__ dist,       // [B,N,K]
    const float* __restrict__ W,          // [10,64]
    const float* __restrict__ bias,       // [64]
    float* __restrict__ out,              // [B,N,64]
    int N)
{
    // Per-warp private tile, 64 points per warp. No block-wide barrier.
    __shared__ float feat_s[BLOCK / 32][10][64];

    const int t = threadIdx.x;
    const int w = t >> 5;
    const int l = t & 31;

    const long long base_pt = (long long)blockIdx.x * PTS_PER_BLOCK;  // inside one batch
    const int bb = (int)(base_pt / N);
    const int n0 = (int)(base_pt % N) + t;          // first point
    const int n1 = n0 + BLOCK;                      // second point

    const float4* xb = g_xyz4 + (size_t)bb * N;

    const float4 s0 = __ldg(xb + n0);
    const float4 s1 = __ldg(xb + n1);

    const int*   ip0 = idx  + ((size_t)bb * N + n0) * KNN;
    const int*   ip1 = idx  + ((size_t)bb * N + n1) * KNN;
    const float* dp0 = dist + ((size_t)bb * N + n0) * KNN;
    const float* dp1 = dist + ((size_t)bb * N + n1) * KNN;

    float mx0 = -INFINITY, my0 = -INFINITY, mz0 = -INFINITY;
    float nx0 =  INFINITY, ny0 =  INFINITY, nz0 =  INFINITY;
    float md0 = -INFINITY;
    float mx1 = -INFINITY, my1 = -INFINITY, mz1 = -INFINITY;
    float nx1 =  INFINITY, ny1 =  INFINITY, nz1 =  INFINITY;
    float md1 = -INFINITY;

    #pragma unroll
    for (int k = 0; k < KNN; k += 4) {
        int4 jA = *reinterpret_cast<const int4*>(ip0 + k);
        int4 jB = *reinterpret_cast<const int4*>(ip1 + k);
        const float4 a0 = __ldg(xb + jA.x);
        const float4 b0 = __ldg(xb + jA.y);
        const float4 c0 = __ldg(xb + jA.z);
        const float4 d0 = __ldg(xb + jA.w);
        const float4 a1 = __ldg(xb + jB.x);
        const float4 b1 = __ldg(xb + jB.y);
        const float4 c1 = __ldg(xb + jB.z);
        const float4 d1 = __ldg(xb + jB.w);

        mx0 = fmaxf(fmaxf(fmaxf(mx0, a0.x), fmaxf(b0.x, c0.x)), d0.x);
        my0 = fmaxf(fmaxf(fmaxf(my0, a0.y), fmaxf(b0.y, c0.y)), d0.y);
        mz0 = fmaxf(fmaxf(fmaxf(mz0, a0.z), fmaxf(b0.z, c0.z)), d0.z);
        nx0 = fminf(fminf(fminf(nx0, a0.x), fminf(b0.x, c0.x)), d0.x);
        ny0 = fminf(fminf(fminf(ny0, a0.y), fminf(b0.y, c0.y)), d0.y);
        nz0 = fminf(fminf(fminf(nz0, a0.z), fminf(b0.z, c0.z)), d0.z);

        mx1 = fmaxf(fmaxf(fmaxf(mx1, a1.x), fmaxf(b1.x, c1.x)), d1.x);
        my1 = fmaxf(fmaxf(fmaxf(my1, a1.y), fmaxf(b1.y, c1.y)), d1.y);
        mz1 = fmaxf(fmaxf(fmaxf(mz1, a1.z), fmaxf(b1.z, c1.z)), d1.z);
        nx1 = fminf(fminf(fminf(nx1, a1.x), fminf(b1.x, c1.x)), d1.x);
        ny1 = fminf(fminf(fminf(ny1, a1.y), fminf(b1.y, c1.y)), d1.y);
        nz1 = fminf(fminf(fminf(nz1, a1.z), fminf(b1.z, c1.z)), d1.z);
    }

    #pragma unroll
    for (int k = 0; k < KNN; k += 4) {
        float4 dA = *reinterpret_cast<const float4*>(dp0 + k);
        float4 dB = *reinterpret_cast<const float4*>(dp1 + k);
        md0 = fmaxf(md0, fmaxf(fmaxf(dA.x, dA.y), fmaxf(dA.z, dA.w)));
        md1 = fmaxf(md1, fmaxf(fmaxf(dB.x, dB.y), fmaxf(dB.z, dB.w)));
    }

    feat_s[w][0][l] = s0.x;        feat_s[w][0][32 + l] = s1.x;
    feat_s[w][1][l] = s0.y;        feat_s[w][1][32 + l] = s1.y;
    feat_s[w][2][l] = s0.z;        feat_s[w][2][32 + l] = s1.z;
    feat_s[w][3][l] = mx0;         feat_s[w][3][32 + l] = mx1;
    feat_s[w][4][l] = my0;         feat_s[w][4][32 + l] = my1;
    feat_s[w][5][l] = mz0;         feat_s[w][5][32 + l] = mz1;
    feat_s[w][6][l] = s0.x - nx0;  feat_s[w][6][32 + l] = s1.x - nx1;
    feat_s[w][7][l] = s0.y - ny0;  feat_s[w][7][32 + l] = s1.y - ny1;
    feat_s[w][8][l] = s0.z - nz0;  feat_s[w][8][32 + l] = s1.z - nz1;
    feat_s[w][9][l] = md0;         feat_s[w][9][32 + l] = md1;

    __syncwarp();

    // Phase 2 (per-warp): lane l owns channels {2l, 2l+1}.
    const float2* W2 = reinterpret_cast<const float2*>(W);
    float2 wc[10];
    #pragma unroll
    for (int c = 0; c < 10; c++) wc[c] = __ldg(W2 + c * 32 + l);
    const float2 bv = __ldg(reinterpret_cast<const float2*>(bias) + l);

    // First 32-point run: points base_pt + w*32 ...
    float2* ob0 = reinterpret_cast<float2*>(out + (base_pt + (long long)w * 32) * HID);
    // Second run: points base_pt + 256 + w*32 ...
    float2* ob1 = reinterpret_cast<float2*>(out + (base_pt + BLOCK + (long long)w * 32) * HID);

    #pragma unroll 8
    for (int p = 0; p < 32; p++) {
        float2 acc = bv;
        #pragma unroll
        for (int c = 0; c < 10; c++) {
            const float f = feat_s[w][c][p];
            acc.x = fmaf(f, wc[c].x, acc.x);
            acc.y = fmaf(f, wc[c].y, acc.y);
        }
        acc.x = fmaxf(acc.x, 0.0f);
        acc.y = fmaxf(acc.y, 0.0f);
        ob0[p * 32 + l] = acc;
    }

    #pragma unroll 8
    for (int p = 0; p < 32; p++) {
        float2 acc = bv;
        #pragma unroll
        for (int c = 0; c < 10; c++) {
            const float f = feat_s[w][c][32 + p];
            acc.x = fmaf(f, wc[c].x, acc.x);
            acc.y = fmaf(f, wc[c].y, acc.y);
        }
        acc.x = fmaxf(acc.x, 0.0f);
        acc.y = fmaxf(acc.y, 0.0f);
        ob1[p * 32 + l] = acc;
    }
}

extern "C" void kernel_launch(void* const* d_in, const int* in_sizes, int n_in,
                              void* d_out, int out_size) {
    const float* pos  = (const float*)d_in[0];   // [B,3,N] f32
    const int*   idx  = (const int*)d_in[1];     // [B,N,K] i32
    const float* dist = (const float*)d_in[2];   // [B,N,K] f32
    const float* W    = (const float*)d_in[3];   // [10,64] f32
    const float* bias = (const float*)d_in[4];   // [64]    f32
    float*       out  = (float*)d_out;           // [B,N,64] f32

    const int N  = NPTS;
    const long long BN = (long long)out_size / HID;   // B*N total points

    transpose_pos_kernel<<<(int)(BN / 1024), 256>>>(pos, N);
    point_embed_kernel<<<(int)(BN / PTS_PER_BLOCK), BLOCK>>>(idx, dist, W, bias, out, N);
}